// round 8
// baseline (speedup 1.0000x reference)
#include <cuda_runtime.h>
#include <cstdint>
#include <math.h>

#define HID 1024
#define KD  1024
#define NLEAF 8192
#define DEPTH 13

// ======================= device scratch =============================================
__device__ float g_h[2][NLEAF * HID];
__device__ float g_c[2][NLEAF * HID];
__device__ float g_hs[(NLEAF / 2) * HID];      // pair-summed child h (tf32-rounded)
__device__ float g_xw[(size_t)NLEAF * 4 * HID];
__device__ float g_g3[(NLEAF / 2) * 3 * HID];
__device__ float g_gf[NLEAF * HID];
__device__ float g_wcat[4 * HID * KD];         // tf32-rounded [Wi;Wo;Wu;Wf]
__device__ float g_ucat3[3 * HID * KD];        // tf32-rounded [Ui;Uo;Uu]
__device__ float g_uf[HID * KD];               // tf32-rounded Uf
__device__ float g_tok[NLEAF * KD];            // tf32-rounded tokens
__device__ float g_opg[4 * 4 * HID];
__device__ float g_lc3[3 * HID];
__device__ float g_lf[2 * HID];

__device__ __forceinline__ float sigf(float x) { return 1.0f / (1.0f + expf(-x)); }

__device__ __forceinline__ uint32_t f2tf(float x) {
    uint32_t r;
    asm("cvt.rna.tf32.f32 %0, %1;" : "=r"(r) : "f"(x));
    return r;
}
__device__ __forceinline__ float f2tf_f(float x) { return __uint_as_float(f2tf(x)); }
__device__ __forceinline__ uint32_t smem_u32(const void* p) {
    uint32_t a;
    asm("{ .reg .u64 t; cvta.to.shared.u64 t, %1; cvt.u32.u64 %0, t; }" : "=r"(a) : "l"(p));
    return a;
}
__device__ __forceinline__ void cp_async16(uint32_t dst, const void* src, int src_bytes) {
    asm volatile("cp.async.cg.shared.global [%0], [%1], 16, %2;"
                 :: "r"(dst), "l"(src), "r"(src_bytes) : "memory");
}

// ======================= precompute (exact fp32) ====================================
__global__ void precompute_kernel(
    const float* __restrict__ W_i, const float* __restrict__ W_o,
    const float* __restrict__ W_u, const float* __restrict__ W_f,
    const float* __restrict__ U_i, const float* __restrict__ U_o,
    const float* __restrict__ U_u, const float* __restrict__ U_f,
    const float* __restrict__ b_i, const float* __restrict__ b_o,
    const float* __restrict__ b_u, const float* __restrict__ b_f,
    const float* __restrict__ op_emb, const float* __restrict__ h_init)
{
    int t = blockIdx.x * blockDim.x + threadIdx.x;
    if (t < 4 * 4 * HID) {
        int k = t >> 12; int rem = t & 4095; int g = rem >> 10; int hh = rem & 1023;
        const float* W = (g == 0) ? W_i : (g == 1) ? W_o : (g == 2) ? W_u : W_f;
        const float* b = (g == 0) ? b_i : (g == 1) ? b_o : (g == 2) ? b_u : b_f;
        const float* x = op_emb + k * KD;
        const float* w = W + (size_t)hh * KD;
        float acc = b[hh];
        for (int kk = 0; kk < KD; kk++) acc += x[kk] * w[kk];
        g_opg[t] = acc;
    } else if (t < 4 * 4 * HID + 3 * HID) {
        int t2 = t - 4 * 4 * HID; int g = t2 >> 10; int hh = t2 & 1023;
        const float* U = (g == 0) ? U_i : (g == 1) ? U_o : U_u;
        const float* b = (g == 0) ? b_i : (g == 1) ? b_o : b_u;
        const float* u = U + (size_t)hh * KD;
        float acc = b[hh];
        for (int kk = 0; kk < KD; kk++) acc += (h_init[kk] + h_init[KD + kk]) * u[kk];
        g_lc3[t2] = acc;
    } else if (t < 4 * 4 * HID + 3 * HID + 2 * HID) {
        int t2 = t - (4 * 4 * HID + 3 * HID); int ci = t2 >> 10; int hh = t2 & 1023;
        const float* u = U_f + (size_t)hh * KD;
        float acc = b_f[hh];
        for (int kk = 0; kk < KD; kk++) acc += h_init[ci * KD + kk] * u[kk];
        g_lf[t2] = acc;
    }
}

// ======== convert all GEMM operands to tf32-rounded fp32 (one pass, float4) =========
// segments (in float4 units): wcat 4x256K | ucat3 3x256K | uf 256K | tok 2M
__global__ void conv_tf32_kernel(
    const float* __restrict__ W_i, const float* __restrict__ W_o,
    const float* __restrict__ W_u, const float* __restrict__ W_f,
    const float* __restrict__ U_i, const float* __restrict__ U_o,
    const float* __restrict__ U_u, const float* __restrict__ U_f,
    const float* __restrict__ tokens)
{
    const int SEG = (HID * KD) / 4;                       // 262144 float4
    int idx = blockIdx.x * blockDim.x + threadIdx.x;      // < 16*SEG
    const float4* src;
    float4* dst;
    if (idx < 4 * SEG) {
        int s = idx / SEG, r = idx % SEG;
        src = (const float4*)((s == 0) ? W_i : (s == 1) ? W_o : (s == 2) ? W_u : W_f) + r;
        dst = (float4*)g_wcat + (size_t)s * SEG + r;
    } else if (idx < 7 * SEG) {
        int s = (idx - 4 * SEG) / SEG, r = (idx - 4 * SEG) % SEG;
        src = (const float4*)((s == 0) ? U_i : (s == 1) ? U_o : U_u) + r;
        dst = (float4*)g_ucat3 + (size_t)s * SEG + r;
    } else if (idx < 8 * SEG) {
        src = (const float4*)U_f + (idx - 7 * SEG);
        dst = (float4*)g_uf + (idx - 7 * SEG);
    } else {
        src = (const float4*)tokens + (idx - 8 * SEG);
        dst = (float4*)g_tok + (idx - 8 * SEG);
    }
    float4 v = *src;
    v.x = f2tf_f(v.x); v.y = f2tf_f(v.y); v.z = f2tf_f(v.z); v.w = f2tf_f(v.w);
    *dst = v;
}

// ======================= tf32 mma.sync GEMM, C[M][N] = A' @ B^T =====================
// Inputs are already tf32-rounded fp32 -> raw bit loads feed mma directly.
// GATHER=0: A row r = A[r];  GATHER=1: A row r = A[ids[r]].
// CTA 128x128, K-chunk 32, 3-stage cp.async, 256 threads, 8 warps of 32x64 warptiles.
// SMEM rows padded to 36 words -> fragment lds bank = 4*gid + tig (conflict-free).
static constexpr int SMEM_STRIDE = 36;
static constexpr int STAGE_WORDS = 256 * SMEM_STRIDE;              // 9216 words
static constexpr int NSTAGE = 3;
static constexpr int GEMM_SMEM_BYTES = NSTAGE * STAGE_WORDS * 4;   // 110592

__device__ __forceinline__ void mma_tf32(float* c, const uint32_t* a, const uint32_t* b) {
    asm volatile(
        "mma.sync.aligned.m16n8k8.row.col.f32.tf32.tf32.f32 "
        "{%0,%1,%2,%3}, {%4,%5,%6,%7}, {%8,%9}, {%0,%1,%2,%3};"
        : "+f"(c[0]), "+f"(c[1]), "+f"(c[2]), "+f"(c[3])
        : "r"(a[0]), "r"(a[1]), "r"(a[2]), "r"(a[3]), "r"(b[0]), "r"(b[1]));
}

template <int GATHER>
__global__ void __launch_bounds__(256, 2)
mma_gemm(const float* __restrict__ A, const float* __restrict__ B,
         float* __restrict__ C, int M, int N, const int* __restrict__ ids)
{
    extern __shared__ __align__(16) uint32_t sm[];
    const int tid  = threadIdx.x;
    const int wid  = tid >> 5;
    const int lane = tid & 31;
    const int m0 = blockIdx.y * 128;
    const int n0 = blockIdx.x * 128;

    // ---- loader: 1 thread per row (0-127 A, 128-255 B), 32 floats = 8 x 16B ----
    const float* src;
    int srcsz = 16;
    if (tid < 128) {
        const int r = m0 + tid;
        const bool ok = r < M;
        const int rr = ok ? (GATHER ? ids[r] : r) : 0;
        src = A + (size_t)rr * KD;
        srcsz = ok ? 16 : 0;
    } else {
        src = B + (size_t)(n0 + tid - 128) * KD;
    }
    const uint32_t dbase = smem_u32(sm) + (uint32_t)(tid * SMEM_STRIDE) * 4;

    auto issue = [&](int it) {
        const uint32_t d = dbase + (uint32_t)(it % NSTAGE) * (STAGE_WORDS * 4);
        const float* p = src + it * 32;
        #pragma unroll
        for (int j = 0; j < 8; j++)
            cp_async16(d + j * 16, p + j * 4, srcsz);
        asm volatile("cp.async.commit_group;" ::: "memory");
    };

    // ---- warp tiling: 4 warps along M (32 each), 2 along N (64 each) ----
    const int wm  = (wid & 3) * 32;
    const int wn  = (wid >> 2) * 64;
    const int gid = lane >> 2;
    const int tig = lane & 3;

    float acc[2][8][4];
    #pragma unroll
    for (int mi = 0; mi < 2; mi++)
        #pragma unroll
        for (int ni = 0; ni < 8; ni++)
            #pragma unroll
            for (int e = 0; e < 4; e++) acc[mi][ni][e] = 0.0f;

    auto compute = [&](int s) {
        const uint32_t* st = sm + s * STAGE_WORDS;
        #pragma unroll
        for (int kk = 0; kk < 32; kk += 8) {
            uint32_t af[2][4], bf[8][2];
            #pragma unroll
            for (int mi = 0; mi < 2; mi++) {
                const uint32_t* ap = st + (wm + mi * 16 + gid) * SMEM_STRIDE + kk + tig;
                af[mi][0] = ap[0];
                af[mi][1] = ap[8 * SMEM_STRIDE];
                af[mi][2] = ap[4];
                af[mi][3] = ap[8 * SMEM_STRIDE + 4];
            }
            #pragma unroll
            for (int ni = 0; ni < 8; ni++) {
                const uint32_t* bp = st + (128 + wn + ni * 8 + gid) * SMEM_STRIDE + kk + tig;
                bf[ni][0] = bp[0];
                bf[ni][1] = bp[4];
            }
            #pragma unroll
            for (int mi = 0; mi < 2; mi++)
                #pragma unroll
                for (int ni = 0; ni < 8; ni++)
                    mma_tf32(acc[mi][ni], af[mi], bf[ni]);
        }
    };

    issue(0);
    issue(1);
    #pragma unroll 1
    for (int it = 0; it < 32; it++) {
        if (it < 31) { asm volatile("cp.async.wait_group 1;" ::: "memory"); }
        else         { asm volatile("cp.async.wait_group 0;" ::: "memory"); }
        __syncthreads();                     // all warps done with stage (it-1)%3 too
        if (it + 2 < 32) issue(it + 2);      // refill while computing
        compute(it % NSTAGE);
    }

    // ---- epilogue ----
    #pragma unroll
    for (int mi = 0; mi < 2; mi++) {
        const int r0 = m0 + wm + mi * 16 + gid;
        #pragma unroll
        for (int ni = 0; ni < 8; ni++) {
            const int col = n0 + wn + ni * 8 + tig * 2;
            if (r0 < M)
                *(float2*)(C + (size_t)r0 * N + col) = make_float2(acc[mi][ni][0], acc[mi][ni][1]);
            if (r0 + 8 < M)
                *(float2*)(C + (size_t)(r0 + 8) * N + col) = make_float2(acc[mi][ni][2], acc[mi][ni][3]);
        }
    }
}

// ========== gate epilogues (pair-fused; h & hs emitted tf32-rounded) ================
__global__ void leaf_gate_pair_kernel(const float* __restrict__ c_init,
                                      float* __restrict__ c_out, float* __restrict__ h_out,
                                      float* __restrict__ hs_out)
{
    int idx = blockIdx.x * blockDim.x + threadIdx.x;   // < (NLEAF/2)*HID
    int hh = idx & 1023;
    int p = idx >> 10;
    const float ci0 = c_init[hh], ci1 = c_init[HID + hh];
    const float lci = g_lc3[hh], lco = g_lc3[HID + hh], lcu = g_lc3[2 * HID + hh];
    const float lf0 = g_lf[hh], lf1 = g_lf[HID + hh];
    float hsum = 0.0f;
    #pragma unroll
    for (int s = 0; s < 2; s++) {
        const int j = 2 * p + s;
        const float* xw = g_xw + (size_t)j * 4 * HID;
        float i = sigf(xw[hh] + lci);
        float o = sigf(xw[HID + hh] + lco);
        float u = tanhf(xw[2 * HID + hh] + lcu);
        float xf = xw[3 * HID + hh];
        float c = i * u + sigf(xf + lf0) * ci0 + sigf(xf + lf1) * ci1;
        float h = o * tanhf(c);
        c_out[(size_t)j * HID + hh] = c;
        h_out[(size_t)j * HID + hh] = f2tf_f(h);
        hsum += h;
    }
    hs_out[(size_t)p * HID + hh] = f2tf_f(hsum);
}

__global__ void node_gate_pair_kernel(int m, int off, const int* __restrict__ op_ids,
                                      const float* __restrict__ c_in,
                                      float* __restrict__ c_out, float* __restrict__ h_out,
                                      float* __restrict__ hs_out)
{
    int idx = blockIdx.x * blockDim.x + threadIdx.x;
    if (idx >= (m >> 1) * HID) return;
    int hh = idx & 1023;
    int p = idx >> 10;
    float hsum = 0.0f;
    #pragma unroll
    for (int s = 0; s < 2; s++) {
        const int j = 2 * p + s;
        const float* og = g_opg + op_ids[off + j] * 4 * HID;
        const float* g3 = g_g3 + (size_t)j * 3 * HID;
        float i = sigf(og[hh]            + g3[hh]);
        float o = sigf(og[HID + hh]      + g3[HID + hh]);
        float u = tanhf(og[2 * HID + hh] + g3[2 * HID + hh]);
        float xf = og[3 * HID + hh];
        float f0 = sigf(xf + g_gf[(size_t)(2 * j) * HID + hh]);
        float f1 = sigf(xf + g_gf[(size_t)(2 * j + 1) * HID + hh]);
        float c = i * u + f0 * c_in[(size_t)(2 * j) * HID + hh]
                        + f1 * c_in[(size_t)(2 * j + 1) * HID + hh];
        float h = o * tanhf(c);
        c_out[(size_t)j * HID + hh] = c;
        h_out[(size_t)j * HID + hh] = f2tf_f(h);
        hsum += h;
    }
    hs_out[(size_t)p * HID + hh] = f2tf_f(hsum);
}

__global__ void node_gate_root_kernel(const int* __restrict__ op_ids,
                                      const float* __restrict__ c_in,
                                      float* __restrict__ c_out, float* __restrict__ h_out)
{
    int hh = blockIdx.x * blockDim.x + threadIdx.x;
    if (hh >= HID) return;
    const float* og = g_opg + op_ids[0] * 4 * HID;
    float i = sigf(og[hh]            + g_g3[hh]);
    float o = sigf(og[HID + hh]      + g_g3[HID + hh]);
    float u = tanhf(og[2 * HID + hh] + g_g3[2 * HID + hh]);
    float xf = og[3 * HID + hh];
    float f0 = sigf(xf + g_gf[hh]);
    float f1 = sigf(xf + g_gf[HID + hh]);
    float c = i * u + f0 * c_in[hh] + f1 * c_in[HID + hh];
    c_out[hh] = c;
    h_out[hh] = o * tanhf(c);       // final output: full fp32
}

// ======================= host launch ================================================
extern "C" void kernel_launch(void* const* d_in, const int* in_sizes, int n_in,
                              void* d_out, int out_size)
{
    const float* tokens   = (const float*)d_in[0];
    const int*   leaf_ids = (const int*)  d_in[1];
    const int*   op_ids   = (const int*)  d_in[2];
    const float* W_i = (const float*)d_in[3];
    const float* W_o = (const float*)d_in[4];
    const float* W_u = (const float*)d_in[5];
    const float* W_f = (const float*)d_in[6];
    const float* U_i = (const float*)d_in[7];
    const float* U_o = (const float*)d_in[8];
    const float* U_u = (const float*)d_in[9];
    const float* U_f = (const float*)d_in[10];
    const float* b_i = (const float*)d_in[11];
    const float* b_o = (const float*)d_in[12];
    const float* b_u = (const float*)d_in[13];
    const float* b_f = (const float*)d_in[14];
    const float* op_emb = (const float*)d_in[15];
    const float* c_init = (const float*)d_in[16];
    const float* h_init = (const float*)d_in[17];
    float* out = (float*)d_out;

    cudaFuncSetAttribute(mma_gemm<0>, cudaFuncAttributeMaxDynamicSharedMemorySize, GEMM_SMEM_BYTES);
    cudaFuncSetAttribute(mma_gemm<1>, cudaFuncAttributeMaxDynamicSharedMemorySize, GEMM_SMEM_BYTES);

    void* p;
    cudaGetSymbolAddress(&p, g_h);     float* hbase = (float*)p;
    cudaGetSymbolAddress(&p, g_c);     float* cbase = (float*)p;
    cudaGetSymbolAddress(&p, g_hs);    float* hsp   = (float*)p;
    cudaGetSymbolAddress(&p, g_xw);    float* xw    = (float*)p;
    cudaGetSymbolAddress(&p, g_g3);    float* g3p   = (float*)p;
    cudaGetSymbolAddress(&p, g_gf);    float* gfp   = (float*)p;
    cudaGetSymbolAddress(&p, g_wcat);  float* wcat  = (float*)p;
    cudaGetSymbolAddress(&p, g_ucat3); float* ucat3 = (float*)p;
    cudaGetSymbolAddress(&p, g_uf);    float* ufp   = (float*)p;
    cudaGetSymbolAddress(&p, g_tok);   float* tokp  = (float*)p;

    float* hbuf[2] = { hbase, hbase + (size_t)NLEAF * HID };
    float* cbuf[2] = { cbase, cbase + (size_t)NLEAF * HID };

    // convert weights + tokens to tf32-rounded fp32 (float4 grid: 16*SEG/4 per block)
    conv_tf32_kernel<<<(16 * (HID * KD / 4)) / 256, 256>>>(
        W_i, W_o, W_u, W_f, U_i, U_o, U_u, U_f, tokens);
    precompute_kernel<<<84, 256>>>(W_i, W_o, W_u, W_f, U_i, U_o, U_u, U_f,
                                   b_i, b_o, b_u, b_f, op_emb, h_init);

    // Leaf level: XW = tok_tf32[leaf_ids] @ Wcat^T  (M=8192, N=4096)
    mma_gemm<1><<<dim3(4 * HID / 128, NLEAF / 128), 256, GEMM_SMEM_BYTES>>>(
        tokp, wcat, xw, NLEAF, 4 * HID, leaf_ids);
    leaf_gate_pair_kernel<<<(NLEAF / 2) * HID / 256, 256>>>(c_init, cbuf[0], hbuf[0], hsp);

    int cur = 0;
    for (int l = DEPTH - 1; l >= 0; l--) {
        const int m = 1 << l;
        const int off = m - 1;
        const int nxt = cur ^ 1;
        // G3[m][3072] = hs @ [Ui;Uo;Uu]^T
        mma_gemm<0><<<dim3(3 * HID / 128, (m + 127) / 128), 256, GEMM_SMEM_BYTES>>>(
            hsp, ucat3, g3p, m, 3 * HID, nullptr);
        // Gf[2m][1024] = h_child @ Uf^T
        mma_gemm<0><<<dim3(HID / 128, (2 * m + 127) / 128), 256, GEMM_SMEM_BYTES>>>(
            hbuf[cur], ufp, gfp, 2 * m, HID, nullptr);
        if (m > 1) {
            node_gate_pair_kernel<<<((m / 2) * HID + 255) / 256, 256>>>(
                m, off, op_ids, cbuf[cur], cbuf[nxt], hbuf[nxt], hsp);
        } else {
            node_gate_root_kernel<<<4, 256>>>(op_ids, cbuf[cur], cbuf[nxt], hbuf[nxt]);
        }
        cur = nxt;
    }

    cudaMemcpyAsync(out,       cbuf[cur], HID * sizeof(float), cudaMemcpyDeviceToDevice, 0);
    cudaMemcpyAsync(out + HID, hbuf[cur], HID * sizeof(float), cudaMemcpyDeviceToDevice, 0);
}

// round 9
// speedup vs baseline: 1.1702x; 1.1702x over previous
#include <cuda_runtime.h>
#include <cstdint>
#include <math.h>

#define HID 1024
#define KD  1024
#define NLEAF 8192
#define DEPTH 13

// k-permutation within each 8-float group: [k0,k4,k1,k5,k2,k6,k3,k7]
// logical k -> physical position (bijective, applied to every GEMM operand row)
#define KPERM(k) (((k) & ~7) | (((k) & 3) << 1) | (((k) >> 2) & 1))

// ======================= device scratch =============================================
__device__ float g_h[2][NLEAF * HID];
__device__ float g_c[2][NLEAF * HID];
__device__ float g_hs[(NLEAF / 2) * HID];      // pair-summed child h (tf32, k-permuted)
__device__ float g_xw[(size_t)NLEAF * 4 * HID];
__device__ float g_g3[(NLEAF / 2) * 3 * HID];
__device__ float g_gf[NLEAF * HID];
__device__ float g_wcat[4 * HID * KD];         // tf32, k-permuted [Wi;Wo;Wu;Wf]
__device__ float g_ucat3[3 * HID * KD];        // tf32, k-permuted [Ui;Uo;Uu]
__device__ float g_uf[HID * KD];               // tf32, k-permuted Uf
__device__ float g_tok[NLEAF * KD];            // tf32, k-permuted tokens
__device__ float g_opg[4 * 4 * HID];
__device__ float g_lc3[3 * HID];
__device__ float g_lf[2 * HID];

__device__ __forceinline__ float sigf(float x) { return 1.0f / (1.0f + expf(-x)); }

__device__ __forceinline__ uint32_t f2tf(float x) {
    uint32_t r;
    asm("cvt.rna.tf32.f32 %0, %1;" : "=r"(r) : "f"(x));
    return r;
}
__device__ __forceinline__ float f2tf_f(float x) { return __uint_as_float(f2tf(x)); }
__device__ __forceinline__ uint32_t smem_u32(const void* p) {
    uint32_t a;
    asm("{ .reg .u64 t; cvta.to.shared.u64 t, %1; cvt.u32.u64 %0, t; }" : "=r"(a) : "l"(p));
    return a;
}
__device__ __forceinline__ void cp_async16(uint32_t dst, const void* src, int src_bytes) {
    asm volatile("cp.async.cg.shared.global [%0], [%1], 16, %2;"
                 :: "r"(dst), "l"(src), "r"(src_bytes) : "memory");
}

// ======================= precompute (exact fp32, original layouts) ==================
__global__ void precompute_kernel(
    const float* __restrict__ W_i, const float* __restrict__ W_o,
    const float* __restrict__ W_u, const float* __restrict__ W_f,
    const float* __restrict__ U_i, const float* __restrict__ U_o,
    const float* __restrict__ U_u, const float* __restrict__ U_f,
    const float* __restrict__ b_i, const float* __restrict__ b_o,
    const float* __restrict__ b_u, const float* __restrict__ b_f,
    const float* __restrict__ op_emb, const float* __restrict__ h_init)
{
    int t = blockIdx.x * blockDim.x + threadIdx.x;
    if (t < 4 * 4 * HID) {
        int k = t >> 12; int rem = t & 4095; int g = rem >> 10; int hh = rem & 1023;
        const float* W = (g == 0) ? W_i : (g == 1) ? W_o : (g == 2) ? W_u : W_f;
        const float* b = (g == 0) ? b_i : (g == 1) ? b_o : (g == 2) ? b_u : b_f;
        const float* x = op_emb + k * KD;
        const float* w = W + (size_t)hh * KD;
        float acc = b[hh];
        for (int kk = 0; kk < KD; kk++) acc += x[kk] * w[kk];
        g_opg[t] = acc;
    } else if (t < 4 * 4 * HID + 3 * HID) {
        int t2 = t - 4 * 4 * HID; int g = t2 >> 10; int hh = t2 & 1023;
        const float* U = (g == 0) ? U_i : (g == 1) ? U_o : U_u;
        const float* b = (g == 0) ? b_i : (g == 1) ? b_o : b_u;
        const float* u = U + (size_t)hh * KD;
        float acc = b[hh];
        for (int kk = 0; kk < KD; kk++) acc += (h_init[kk] + h_init[KD + kk]) * u[kk];
        g_lc3[t2] = acc;
    } else if (t < 4 * 4 * HID + 3 * HID + 2 * HID) {
        int t2 = t - (4 * 4 * HID + 3 * HID); int ci = t2 >> 10; int hh = t2 & 1023;
        const float* u = U_f + (size_t)hh * KD;
        float acc = b_f[hh];
        for (int kk = 0; kk < KD; kk++) acc += h_init[ci * KD + kk] * u[kk];
        g_lf[t2] = acc;
    }
}

// ===== convert GEMM operands: tf32-round + k-permute (scatter within 8-group) =======
// segments (float4 units): wcat 4xSEG | ucat3 3xSEG | uf SEG | tok 2xSEG
__global__ void conv_tf32_kernel(
    const float* __restrict__ W_i, const float* __restrict__ W_o,
    const float* __restrict__ W_u, const float* __restrict__ W_f,
    const float* __restrict__ U_i, const float* __restrict__ U_o,
    const float* __restrict__ U_u, const float* __restrict__ U_f,
    const float* __restrict__ tokens)
{
    const int SEG = (HID * KD) / 4;                       // 262144 float4
    int idx = blockIdx.x * blockDim.x + threadIdx.x;      // < 16*SEG
    const float4* src;
    float* dst;
    size_t off4;
    if (idx < 4 * SEG) {
        int s = idx / SEG; off4 = idx % SEG;
        src = (const float4*)((s == 0) ? W_i : (s == 1) ? W_o : (s == 2) ? W_u : W_f) + off4;
        dst = g_wcat + (size_t)s * (HID * KD);
    } else if (idx < 7 * SEG) {
        int s = (idx - 4 * SEG) / SEG; off4 = (idx - 4 * SEG) % SEG;
        src = (const float4*)((s == 0) ? U_i : (s == 1) ? U_o : U_u) + off4;
        dst = g_ucat3 + (size_t)s * (HID * KD);
    } else if (idx < 8 * SEG) {
        off4 = idx - 7 * SEG;
        src = (const float4*)U_f + off4;
        dst = g_uf;
    } else {
        off4 = idx - 8 * SEG;
        src = (const float4*)tokens + off4;
        dst = g_tok;
    }
    float4 v = *src;
    const size_t i = off4 * 4;                 // linear elem index; i % 4 == 0
    const size_t base = i & ~(size_t)7;
    const int o = (i & 4) ? 1 : 0;             // group half -> odd/even slots
    dst[base + o + 0] = f2tf_f(v.x);
    dst[base + o + 2] = f2tf_f(v.y);
    dst[base + o + 4] = f2tf_f(v.z);
    dst[base + o + 6] = f2tf_f(v.w);
}

// ======================= tf32 mma.sync GEMM core, C[M][N] = A' @ B^T ================
// Operands are tf32-rounded, k-permuted fp32. GATHER: A row r = A[ids[r]].
// CTA 128x128 tile, K-chunk 32, 3-stage cp.async, 512 threads, 16 warps of 32x32.
// SMEM_STRIDE=40 (== 8 mod 32) -> uint2 fragment LDS.64 conflict-free.
static constexpr int SMEM_STRIDE = 40;
static constexpr int STAGE_WORDS = 256 * SMEM_STRIDE;              // 10240 words
static constexpr int NSTAGE = 3;
static constexpr int GEMM_SMEM_BYTES = NSTAGE * STAGE_WORDS * 4;   // 122880

__device__ __forceinline__ void mma_tf32(float* c, uint32_t a0, uint32_t a1,
                                         uint32_t a2, uint32_t a3,
                                         uint32_t b0, uint32_t b1) {
    asm volatile(
        "mma.sync.aligned.m16n8k8.row.col.f32.tf32.tf32.f32 "
        "{%0,%1,%2,%3}, {%4,%5,%6,%7}, {%8,%9}, {%0,%1,%2,%3};"
        : "+f"(c[0]), "+f"(c[1]), "+f"(c[2]), "+f"(c[3])
        : "r"(a0), "r"(a1), "r"(a2), "r"(a3), "r"(b0), "r"(b1));
}

template <int GATHER>
__device__ __forceinline__ void gemm_tile(
    const float* __restrict__ A, const float* __restrict__ B, float* __restrict__ C,
    int M, int N, int m0, int n0, const int* __restrict__ ids, uint32_t* sm)
{
    const int tid  = threadIdx.x;
    const int wid  = tid >> 5;
    const int lane = tid & 31;

    // ---- loader: 2 threads/row (256 rows: 0-127 A, 128-255 B), 16 floats each ----
    const int lrow = tid >> 1;
    const int fcol = (tid & 1) * 16;
    const float* src;
    int srcsz = 16;
    if (lrow < 128) {
        const int r = m0 + lrow;
        const bool ok = r < M;
        const int rr = ok ? (GATHER ? ids[r] : r) : 0;
        src = A + (size_t)rr * KD + fcol;
        srcsz = ok ? 16 : 0;
    } else {
        src = B + (size_t)(n0 + lrow - 128) * KD + fcol;
    }
    const uint32_t dbase = smem_u32(sm) + (uint32_t)(lrow * SMEM_STRIDE + fcol) * 4;

    auto issue = [&](int it) {
        const uint32_t d = dbase + (uint32_t)(it % NSTAGE) * (STAGE_WORDS * 4);
        const float* p = src + it * 32;
        #pragma unroll
        for (int j = 0; j < 4; j++)
            cp_async16(d + j * 16, p + j * 4, srcsz);
        asm volatile("cp.async.commit_group;" ::: "memory");
    };

    // ---- 16 warps: 4 along M x 4 along N, 32x32 warptiles ----
    const int wm  = (wid & 3) * 32;
    const int wn  = (wid >> 2) * 32;
    const int gid = lane >> 2;
    const int tig = lane & 3;

    float acc[2][4][4];
    #pragma unroll
    for (int mi = 0; mi < 2; mi++)
        #pragma unroll
        for (int ni = 0; ni < 4; ni++)
            #pragma unroll
            for (int e = 0; e < 4; e++) acc[mi][ni][e] = 0.0f;

    auto compute = [&](int s) {
        const uint32_t* st = sm + s * STAGE_WORDS;
        #pragma unroll
        for (int kk = 0; kk < 32; kk += 8) {
            // permuted layout: (k=tig, k=tig+4) adjacent at word offset kk + 2*tig
            uint2 a[2][2], b[4];
            #pragma unroll
            for (int mi = 0; mi < 2; mi++) {
                const uint32_t* ap = st + (wm + mi * 16 + gid) * SMEM_STRIDE + kk + 2 * tig;
                a[mi][0] = *(const uint2*)ap;                       // (row, tig) (row, tig+4)
                a[mi][1] = *(const uint2*)(ap + 8 * SMEM_STRIDE);   // (row+8, ...)
            }
            #pragma unroll
            for (int ni = 0; ni < 4; ni++)
                b[ni] = *(const uint2*)(st + (128 + wn + ni * 8 + gid) * SMEM_STRIDE
                                        + kk + 2 * tig);
            #pragma unroll
            for (int mi = 0; mi < 2; mi++)
                #pragma unroll
                for (int ni = 0; ni < 4; ni++)
                    mma_tf32(acc[mi][ni],
                             a[mi][0].x, a[mi][1].x, a[mi][0].y, a[mi][1].y,
                             b[ni].x, b[ni].y);
        }
    };

    issue(0);
    issue(1);
    #pragma unroll 1
    for (int it = 0; it < 32; it++) {
        if (it < 31) { asm volatile("cp.async.wait_group 1;" ::: "memory"); }
        else         { asm volatile("cp.async.wait_group 0;" ::: "memory"); }
        __syncthreads();
        if (it + 2 < 32) issue(it + 2);
        compute(it % NSTAGE);
    }

    #pragma unroll
    for (int mi = 0; mi < 2; mi++) {
        const int r0 = m0 + wm + mi * 16 + gid;
        #pragma unroll
        for (int ni = 0; ni < 4; ni++) {
            const int col = n0 + wn + ni * 8 + tig * 2;
            if (r0 < M)
                *(float2*)(C + (size_t)r0 * N + col) = make_float2(acc[mi][ni][0], acc[mi][ni][1]);
            if (r0 + 8 < M)
                *(float2*)(C + (size_t)(r0 + 8) * N + col) = make_float2(acc[mi][ni][2], acc[mi][ni][3]);
        }
    }
}

// leaf GEMM (gathered tokens)
__global__ void __launch_bounds__(512, 1)
leaf_gemm(const float* __restrict__ A, const float* __restrict__ B,
          float* __restrict__ C, int M, int N, const int* __restrict__ ids)
{
    extern __shared__ __align__(16) uint32_t sm[];
    gemm_tile<1>(A, B, C, M, N, blockIdx.y * 128, blockIdx.x * 128, ids, sm);
}

// merged per-level GEMM: blocks x<24 do G3 (hs@U3^T), x>=24 do Gf (h@Uf^T)
__global__ void __launch_bounds__(512, 1)
level_gemm(const float* __restrict__ hs, const float* __restrict__ h,
           const float* __restrict__ U3, const float* __restrict__ Uf,
           float* __restrict__ g3, float* __restrict__ gf, int m)
{
    extern __shared__ __align__(16) uint32_t sm[];
    const int bx = blockIdx.x;
    const int m0 = blockIdx.y * 128;
    if (bx < 24) {
        if (m0 >= m) return;
        gemm_tile<0>(hs, U3, g3, m, 3 * HID, m0, bx * 128, nullptr, sm);
    } else {
        if (m0 >= 2 * m) return;
        gemm_tile<0>(h, Uf, gf, 2 * m, HID, m0, (bx - 24) * 128, nullptr, sm);
    }
}

// ========== gate epilogues (pair-fused; h & hs emitted tf32-rounded, k-permuted) ====
__global__ void leaf_gate_pair_kernel(const float* __restrict__ c_init,
                                      float* __restrict__ c_out, float* __restrict__ h_out,
                                      float* __restrict__ hs_out)
{
    int idx = blockIdx.x * blockDim.x + threadIdx.x;   // < (NLEAF/2)*HID
    int hh = idx & 1023;
    int p = idx >> 10;
    const int hp = KPERM(hh);                          // permuted k-position
    const float ci0 = c_init[hh], ci1 = c_init[HID + hh];
    const float lci = g_lc3[hh], lco = g_lc3[HID + hh], lcu = g_lc3[2 * HID + hh];
    const float lf0 = g_lf[hh], lf1 = g_lf[HID + hh];
    float hsum = 0.0f;
    #pragma unroll
    for (int s = 0; s < 2; s++) {
        const int j = 2 * p + s;
        const float* xw = g_xw + (size_t)j * 4 * HID;
        float i = sigf(xw[hh] + lci);
        float o = sigf(xw[HID + hh] + lco);
        float u = tanhf(xw[2 * HID + hh] + lcu);
        float xf = xw[3 * HID + hh];
        float c = i * u + sigf(xf + lf0) * ci0 + sigf(xf + lf1) * ci1;
        float h = o * tanhf(c);
        c_out[(size_t)j * HID + hh] = c;
        h_out[(size_t)j * HID + hp] = f2tf_f(h);
        hsum += h;
    }
    hs_out[(size_t)p * HID + hp] = f2tf_f(hsum);
}

__global__ void node_gate_pair_kernel(int m, int off, const int* __restrict__ op_ids,
                                      const float* __restrict__ c_in,
                                      float* __restrict__ c_out, float* __restrict__ h_out,
                                      float* __restrict__ hs_out)
{
    int idx = blockIdx.x * blockDim.x + threadIdx.x;
    if (idx >= (m >> 1) * HID) return;
    int hh = idx & 1023;
    int p = idx >> 10;
    const int hp = KPERM(hh);
    float hsum = 0.0f;
    #pragma unroll
    for (int s = 0; s < 2; s++) {
        const int j = 2 * p + s;
        const float* og = g_opg + op_ids[off + j] * 4 * HID;
        const float* g3 = g_g3 + (size_t)j * 3 * HID;
        float i = sigf(og[hh]            + g3[hh]);
        float o = sigf(og[HID + hh]      + g3[HID + hh]);
        float u = tanhf(og[2 * HID + hh] + g3[2 * HID + hh]);
        float xf = og[3 * HID + hh];
        float f0 = sigf(xf + g_gf[(size_t)(2 * j) * HID + hh]);
        float f1 = sigf(xf + g_gf[(size_t)(2 * j + 1) * HID + hh]);
        float c = i * u + f0 * c_in[(size_t)(2 * j) * HID + hh]
                        + f1 * c_in[(size_t)(2 * j + 1) * HID + hh];
        float h = o * tanhf(c);
        c_out[(size_t)j * HID + hh] = c;
        h_out[(size_t)j * HID + hp] = f2tf_f(h);
        hsum += h;
    }
    hs_out[(size_t)p * HID + hp] = f2tf_f(hsum);
}

__global__ void node_gate_root_kernel(const int* __restrict__ op_ids,
                                      const float* __restrict__ c_in,
                                      float* __restrict__ c_out, float* __restrict__ h_out)
{
    int hh = blockIdx.x * blockDim.x + threadIdx.x;
    if (hh >= HID) return;
    const float* og = g_opg + op_ids[0] * 4 * HID;
    float i = sigf(og[hh]            + g_g3[hh]);
    float o = sigf(og[HID + hh]      + g_g3[HID + hh]);
    float u = tanhf(og[2 * HID + hh] + g_g3[2 * HID + hh]);
    float xf = og[3 * HID + hh];
    float f0 = sigf(xf + g_gf[hh]);
    float f1 = sigf(xf + g_gf[HID + hh]);
    float c = i * u + f0 * c_in[hh] + f1 * c_in[HID + hh];
    c_out[hh] = c;                  // final output: full fp32, natural order
    h_out[hh] = o * tanhf(c);
}

// ======================= host launch ================================================
extern "C" void kernel_launch(void* const* d_in, const int* in_sizes, int n_in,
                              void* d_out, int out_size)
{
    const float* tokens   = (const float*)d_in[0];
    const int*   leaf_ids = (const int*)  d_in[1];
    const int*   op_ids   = (const int*)  d_in[2];
    const float* W_i = (const float*)d_in[3];
    const float* W_o = (const float*)d_in[4];
    const float* W_u = (const float*)d_in[5];
    const float* W_f = (const float*)d_in[6];
    const float* U_i = (const float*)d_in[7];
    const float* U_o = (const float*)d_in[8];
    const float* U_u = (const float*)d_in[9];
    const float* U_f = (const float*)d_in[10];
    const float* b_i = (const float*)d_in[11];
    const float* b_o = (const float*)d_in[12];
    const float* b_u = (const float*)d_in[13];
    const float* b_f = (const float*)d_in[14];
    const float* op_emb = (const float*)d_in[15];
    const float* c_init = (const float*)d_in[16];
    const float* h_init = (const float*)d_in[17];
    float* out = (float*)d_out;

    cudaFuncSetAttribute(leaf_gemm,  cudaFuncAttributeMaxDynamicSharedMemorySize, GEMM_SMEM_BYTES);
    cudaFuncSetAttribute(level_gemm, cudaFuncAttributeMaxDynamicSharedMemorySize, GEMM_SMEM_BYTES);

    void* p;
    cudaGetSymbolAddress(&p, g_h);     float* hbase = (float*)p;
    cudaGetSymbolAddress(&p, g_c);     float* cbase = (float*)p;
    cudaGetSymbolAddress(&p, g_hs);    float* hsp   = (float*)p;
    cudaGetSymbolAddress(&p, g_xw);    float* xw    = (float*)p;
    cudaGetSymbolAddress(&p, g_g3);    float* g3p   = (float*)p;
    cudaGetSymbolAddress(&p, g_gf);    float* gfp   = (float*)p;
    cudaGetSymbolAddress(&p, g_wcat);  float* wcat  = (float*)p;
    cudaGetSymbolAddress(&p, g_ucat3); float* ucat3 = (float*)p;
    cudaGetSymbolAddress(&p, g_uf);    float* ufp   = (float*)p;
    cudaGetSymbolAddress(&p, g_tok);   float* tokp  = (float*)p;

    float* hbuf[2] = { hbase, hbase + (size_t)NLEAF * HID };
    float* cbuf[2] = { cbase, cbase + (size_t)NLEAF * HID };

    // tf32-round + k-permute all GEMM operands; precompute op gate table
    conv_tf32_kernel<<<(16 * (HID * KD / 4)) / 256, 256>>>(
        W_i, W_o, W_u, W_f, U_i, U_o, U_u, U_f, tokens);
    precompute_kernel<<<84, 256>>>(W_i, W_o, W_u, W_f, U_i, U_o, U_u, U_f,
                                   b_i, b_o, b_u, b_f, op_emb, h_init);

    // Leaf level: XW = tok[leaf_ids] @ Wcat^T  (M=8192, N=4096)
    leaf_gemm<<<dim3(4 * HID / 128, NLEAF / 128), 512, GEMM_SMEM_BYTES>>>(
        tokp, wcat, xw, NLEAF, 4 * HID, leaf_ids);
    leaf_gate_pair_kernel<<<(NLEAF / 2) * HID / 256, 256>>>(c_init, cbuf[0], hbuf[0], hsp);

    int cur = 0;
    for (int l = DEPTH - 1; l >= 0; l--) {
        const int m = 1 << l;
        const int off = m - 1;
        const int nxt = cur ^ 1;
        // one launch: G3[m][3072] = hs @ U3^T   AND   Gf[2m][1024] = h @ Uf^T
        level_gemm<<<dim3(32, (2 * m + 127) / 128), 512, GEMM_SMEM_BYTES>>>(
            hsp, hbuf[cur], ucat3, ufp, g3p, gfp, m);
        if (m > 1) {
            node_gate_pair_kernel<<<((m / 2) * HID + 255) / 256, 256>>>(
                m, off, op_ids, cbuf[cur], cbuf[nxt], hbuf[nxt], hsp);
        } else {
            node_gate_root_kernel<<<4, 256>>>(op_ids, cbuf[cur], cbuf[nxt], hbuf[nxt]);
        }
        cur = nxt;
    }

    cudaMemcpyAsync(out,       cbuf[cur], HID * sizeof(float), cudaMemcpyDeviceToDevice, 0);
    cudaMemcpyAsync(out + HID, hbuf[cur], HID * sizeof(float), cudaMemcpyDeviceToDevice, 0);
}